// round 15
// baseline (speedup 1.0000x reference)
#include <cuda_runtime.h>
#include <cstdint>
#include <math.h>

// Problem constants
constexpr int B_   = 16;
constexpr int H_   = 16;
constexpr int HD_  = 128;
constexpr int D_   = 2048;
constexpr int SPAST = 4096;
constexpr int SPLITS = 8;
constexpr int CHUNK  = 512;   // SPAST / SPLITS
constexpr float SCALING = 0.08838834764831845f;  // 128^-0.5

// Scratch (static device globals — no allocation allowed)
__device__ float g_q[B_ * D_];
__device__ float g_attn[B_ * D_];
__device__ float g_pm[B_ * H_ * SPLITS];
__device__ float g_pl[B_ * H_ * SPLITS];
__device__ float g_pacc[B_ * H_ * SPLITS * HD_];

struct GemvArgs {
    const float* W[3];
    const float* bias[3];
    float*       out[3];
    float        scale[3];
};

// ---------------------------------------------------------------------------
// Templated GEMV: 128 threads, 4 warps, RPW rows per warp, smem-transpose
// epilogue (r14's proven win). KSPLIT=1 -> direct bias store; KSPLIT>1 ->
// atomicAdd into bias-preseeded output.
// RPW=4 (ITERS=16): near the FMA-issue ceiling -- used for QKV.
// RPW=2: acc 64->32 regs (~90 total -> 5-6 blocks/SM = 20-24 warps resident)
//        and doubles x-blocks so Wo gets ITERS=8 at KSPLIT=2 -- twice the
//        streaming per DRAM-prologue with 2x the latency-hiding warps.
// ---------------------------------------------------------------------------
template <int KSPLIT, int RPW>
__global__ __launch_bounds__(128) void gemv_kernel(const float* __restrict__ x,
                                                   GemvArgs a) {
    constexpr int BROWS = 4 * RPW;        // rows per block
    constexpr int OUTS  = BROWS * 16;     // outputs per block
    __shared__ float sacc[OUTS][33];      // padded: conflict-free transpose

    int tid  = threadIdx.x;
    int warp = tid >> 5;
    int lane = tid & 31;
    int blk_row0 = blockIdx.x * BROWS;
    int mi   = blk_row0 >> 11;            // which matrix (2048 rows each)
    int o0b  = blk_row0 & 2047;           // block's first row within matrix
    int o0   = o0b + warp * RPW;          // this warp's first row

    const float4* W = (const float4*)a.W[mi];
    const float4* X = (const float4*)x;

    float acc[RPW][16];
#pragma unroll
    for (int r = 0; r < RPW; r++)
#pragma unroll
        for (int b = 0; b < 16; b++) acc[r][b] = 0.f;

    constexpr int ITERS = 16 / KSPLIT;
    int i0 = blockIdx.y * ITERS;

    // Depth-1 prefetch of the RPW weight rows.
    int d4 = i0 * 32 + lane;
    float4 w[RPW];
#pragma unroll
    for (int r = 0; r < RPW; r++)
        w[r] = __ldcs(&W[(size_t)(o0 + r) * 512 + d4]);

#pragma unroll
    for (int ii = 0; ii < ITERS; ii++) {
        float4 c[RPW];
#pragma unroll
        for (int r = 0; r < RPW; r++) c[r] = w[r];
        int dcur = d4;
        if (ii + 1 < ITERS) {
            d4 += 32;
#pragma unroll
            for (int r = 0; r < RPW; r++)
                w[r] = __ldcs(&W[(size_t)(o0 + r) * 512 + d4]);
        }
#pragma unroll
        for (int b = 0; b < 16; b++) {
            float4 xv = X[b * 512 + dcur];
#pragma unroll
            for (int r = 0; r < RPW; r++)
                acc[r][b] += c[r].x * xv.x + c[r].y * xv.y +
                             c[r].z * xv.z + c[r].w * xv.w;
        }
    }

    // ---- smem transpose reduction ----
#pragma unroll
    for (int r = 0; r < RPW; r++)
#pragma unroll
        for (int b = 0; b < 16; b++)
            sacc[warp * RPW * 16 + r * 16 + b][lane] = acc[r][b];
    __syncthreads();

    const float* bias = a.bias[mi];
    float*       out  = a.out[mi];
    float        sc   = a.scale[mi];
#pragma unroll
    for (int k = 0; k < OUTS / 128; k++) {
        int oidx = tid + k * 128;             // [0, OUTS)
        int wr = oidx / (RPW * 16);
        int rr = (oidx >> 4) % RPW;
        int b2 = oidx & 15;
        int row = o0b + wr * RPW + rr;
        float sum = 0.f;
#pragma unroll
        for (int l = 0; l < 32; l++) sum += sacc[oidx][l];
        if (KSPLIT == 1)
            out[b2 * D_ + row] = (sum + bias[row]) * sc;
        else
            atomicAdd(&out[b2 * D_ + row], sum * sc);
    }
}

// ---------------------------------------------------------------------------
// Split-S flash-decode attention partials (proven structure, untouched).
// grid = (256 bh, 8 splits), block = 256 (8 warps). Warp-per-row online
// softmax; each lane owns 4 head-dim elements (float4).
// K/V are a 1 GB single-use stream: __ldcs keeps them out of L2's way.
// ---------------------------------------------------------------------------
__global__ __launch_bounds__(256) void attn_partial_kernel(
    const float* __restrict__ pk, const float* __restrict__ pv,
    const float* __restrict__ mask,
    const float* __restrict__ knew, const float* __restrict__ vnew) {
    int bh    = blockIdx.x;
    int split = blockIdx.y;
    int b     = bh >> 4;
    int h     = bh & 15;
    int warp  = threadIdx.x >> 5;
    int lane  = threadIdx.x & 31;

    const float4* q4p = (const float4*)(g_q + b * D_ + h * HD_);
    float4 q4 = q4p[lane];  // q pre-scaled by SCALING

    size_t base = ((size_t)b * SPAST) * D_ + h * HD_;

    float  m = -1e30f, l = 0.f;
    float4 acc = make_float4(0.f, 0.f, 0.f, 0.f);

    int s0 = split * CHUNK + warp;
    int s_end = split * CHUNK + CHUNK;

#pragma unroll 4
    for (int s = s0; s < s_end; s += 8) {
        const float4* kr = (const float4*)(pk + base + (size_t)s * D_);
        const float4* vr = (const float4*)(pv + base + (size_t)s * D_);
        float4 k4 = __ldcs(&kr[lane]);
        float4 v4 = __ldcs(&vr[lane]);
        float sc = k4.x * q4.x + k4.y * q4.y + k4.z * q4.z + k4.w * q4.w;
        sc += __shfl_xor_sync(0xffffffffu, sc, 16);
        sc += __shfl_xor_sync(0xffffffffu, sc, 8);
        sc += __shfl_xor_sync(0xffffffffu, sc, 4);
        sc += __shfl_xor_sync(0xffffffffu, sc, 2);
        sc += __shfl_xor_sync(0xffffffffu, sc, 1);
        sc += mask[s];
        float nm   = fmaxf(m, sc);
        float corr = __expf(m - nm);
        float p    = __expf(sc - nm);
        m = nm;
        l = l * corr + p;
        acc.x = acc.x * corr + p * v4.x;
        acc.y = acc.y * corr + p * v4.y;
        acc.z = acc.z * corr + p * v4.z;
        acc.w = acc.w * corr + p * v4.w;
    }

    // The new token (s = 4096) lives in the last split, handled by warp 0.
    if (split == SPLITS - 1 && warp == 0) {
        const float4* kr = (const float4*)(knew + b * D_ + h * HD_);
        const float4* vr = (const float4*)(vnew + b * D_ + h * HD_);
        float4 k4 = kr[lane];
        float4 v4 = vr[lane];
        float sc = k4.x * q4.x + k4.y * q4.y + k4.z * q4.z + k4.w * q4.w;
        sc += __shfl_xor_sync(0xffffffffu, sc, 16);
        sc += __shfl_xor_sync(0xffffffffu, sc, 8);
        sc += __shfl_xor_sync(0xffffffffu, sc, 4);
        sc += __shfl_xor_sync(0xffffffffu, sc, 2);
        sc += __shfl_xor_sync(0xffffffffu, sc, 1);
        sc += mask[SPAST];
        float nm   = fmaxf(m, sc);
        float corr = __expf(m - nm);
        float p    = __expf(sc - nm);
        m = nm;
        l = l * corr + p;
        acc.x = acc.x * corr + p * v4.x;
        acc.y = acc.y * corr + p * v4.y;
        acc.z = acc.z * corr + p * v4.z;
        acc.w = acc.w * corr + p * v4.w;
    }

    // Combine the 8 warps of this block.
    __shared__ float  sm_m[8], sm_l[8];
    __shared__ float4 sm_acc[8][32];
    sm_acc[warp][lane] = acc;
    if (lane == 0) { sm_m[warp] = m; sm_l[warp] = l; }
    __syncthreads();

    if (threadIdx.x < HD_) {
        int d = threadIdx.x;
        float M = -1e30f;
#pragma unroll
        for (int w = 0; w < 8; w++) M = fmaxf(M, sm_m[w]);
        float L = 0.f, A = 0.f;
        const float* accf = (const float*)sm_acc;
#pragma unroll
        for (int w = 0; w < 8; w++) {
            float e = __expf(sm_m[w] - M);
            L += sm_l[w] * e;
            A += accf[w * HD_ + d] * e;
        }
        int idx = bh * SPLITS + split;
        g_pacc[idx * HD_ + d] = A;
        if (d == 0) { g_pm[idx] = M; g_pl[idx] = L; }
    }
}

// ---------------------------------------------------------------------------
// Combine the 8 split partials per (b,h) AND seed the final output buffer
// with the Wo bias, so the Wo split-K gemv can pure-atomicAdd.
// ---------------------------------------------------------------------------
__global__ __launch_bounds__(128) void attn_combine_kernel(
    float* __restrict__ out, const float* __restrict__ bo) {
    int bh = blockIdx.x;
    int d  = threadIdx.x;

    int oidx = bh * HD_ + d;          // [0, 32768)
    out[oidx] = bo[oidx & (D_ - 1)];  // seed Wo bias

    float M = -1e30f;
#pragma unroll
    for (int i = 0; i < SPLITS; i++) M = fmaxf(M, g_pm[bh * SPLITS + i]);
    float L = 0.f, A = 0.f;
#pragma unroll
    for (int i = 0; i < SPLITS; i++) {
        float e = __expf(g_pm[bh * SPLITS + i] - M);
        L += g_pl[bh * SPLITS + i] * e;
        A += g_pacc[(bh * SPLITS + i) * HD_ + d] * e;
    }
    int b = bh >> 4, h = bh & 15;
    g_attn[b * D_ + h * HD_ + d] = A / L;
}

// ---------------------------------------------------------------------------
extern "C" void kernel_launch(void* const* d_in, const int* in_sizes, int n_in,
                              void* d_out, int out_size) {
    const float* hs   = (const float*)d_in[0];
    const float* pk   = (const float*)d_in[1];
    const float* pv   = (const float*)d_in[2];
    const float* mask = (const float*)d_in[3];
    const float* Wq   = (const float*)d_in[4];
    const float* bq   = (const float*)d_in[5];
    const float* Wk   = (const float*)d_in[6];
    const float* bk   = (const float*)d_in[7];
    const float* Wv   = (const float*)d_in[8];
    const float* bv   = (const float*)d_in[9];
    const float* Wo   = (const float*)d_in[10];
    const float* bo   = (const float*)d_in[11];

    float* out  = (float*)d_out;          // [0, 32768): attn_output
    float* knew = out + B_ * D_;          // [32768, 65536): new_key
    float* vnew = out + 2 * B_ * D_;      // [65536, 98304): new_value

    float* qptr;  cudaGetSymbolAddress((void**)&qptr, g_q);
    float* aptr;  cudaGetSymbolAddress((void**)&aptr, g_attn);

    // 1. Fused QKV projection: RPW=4, 384 full-length blocks, direct store.
    GemvArgs a;
    a.W[0] = Wq; a.bias[0] = bq; a.out[0] = qptr; a.scale[0] = SCALING;
    a.W[1] = Wk; a.bias[1] = bk; a.out[1] = knew; a.scale[1] = 1.f;
    a.W[2] = Wv; a.bias[2] = bv; a.out[2] = vnew; a.scale[2] = 1.f;
    gemv_kernel<1, 4><<<384, 128>>>(hs, a);

    // 2. Split-S attention partials (the HBM-bound 1.07 GB stream).
    attn_partial_kernel<<<dim3(B_ * H_, SPLITS), 256>>>(pk, pv, mask, knew, vnew);

    // 3. Combine partials + seed out with Wo bias.
    attn_combine_kernel<<<B_ * H_, 128>>>(out, bo);

    // 4. Output projection: RPW=2 -> 256 x-blocks, KSPLIT=2 -> 512 blocks,
    //    ITERS=8 at ~2x the resident warps of the r14 config.
    GemvArgs ao;
    ao.W[0] = Wo; ao.bias[0] = bo; ao.out[0] = out; ao.scale[0] = 1.f;
    ao.W[1] = Wo; ao.bias[1] = bo; ao.out[1] = out; ao.scale[1] = 1.f;
    ao.W[2] = Wo; ao.bias[2] = bo; ao.out[2] = out; ao.scale[2] = 1.f;
    gemv_kernel<2, 2><<<dim3(256, 2), 128>>>(aptr, ao);
}

// round 16
// speedup vs baseline: 1.1895x; 1.1895x over previous
#include <cuda_runtime.h>
#include <cstdint>
#include <math.h>

// Problem constants
constexpr int B_   = 16;
constexpr int H_   = 16;
constexpr int HD_  = 128;
constexpr int D_   = 2048;
constexpr int SPAST = 4096;
constexpr int SPLITS = 8;
constexpr int CHUNK  = 512;   // SPAST / SPLITS
constexpr float SCALING = 0.08838834764831845f;  // 128^-0.5

// Scratch (static device globals — no allocation allowed)
__device__ float g_q[B_ * D_];
__device__ float g_attn[B_ * D_];
__device__ float g_pm[B_ * H_ * SPLITS];
__device__ float g_pl[B_ * H_ * SPLITS];
__device__ float g_pacc[B_ * H_ * SPLITS * HD_];

struct GemvArgs {
    const float* W[3];
    const float* bias[3];
    float*       out[3];
    float        scale[3];
};

// ---------------------------------------------------------------------------
// r14 GEMV exactly (the measured best): 128 threads, 4 warps x 4 rows,
// depth-1 prefetch, smem-transpose epilogue.
// KSPLIT=1 -> direct bias store; KSPLIT>1 -> atomicAdd into preseeded out.
// (r15 showed RPW=2 halves per-warp weight-MLP and loses: occupancy and
// per-warp loads-in-flight multiply; 4 rows x KSPLIT=4 is the sweet spot.)
// ---------------------------------------------------------------------------
template <int KSPLIT>
__global__ __launch_bounds__(128) void gemv_kernel(const float* __restrict__ x,
                                                   GemvArgs a) {
    __shared__ float sacc[256][33];   // 256 outputs x 32 lane-partials, pad 33

    int tid  = threadIdx.x;
    int warp = tid >> 5;
    int lane = tid & 31;
    int blk_row0 = blockIdx.x * 16;
    int mi   = blk_row0 >> 11;        // which matrix (2048 rows each)
    int o0b  = blk_row0 & 2047;       // block's first row within matrix
    int o0   = o0b + warp * 4;        // this warp's first row

    const float4* W = (const float4*)a.W[mi];
    const float4* X = (const float4*)x;

    float acc[4][16];
#pragma unroll
    for (int r = 0; r < 4; r++)
#pragma unroll
        for (int b = 0; b < 16; b++) acc[r][b] = 0.f;

    constexpr int ITERS = 16 / KSPLIT;
    int i0 = blockIdx.y * ITERS;

    // Depth-1 prefetch of the four weight rows.
    int d4 = i0 * 32 + lane;
    float4 w0 = __ldcs(&W[(size_t)(o0 + 0) * 512 + d4]);
    float4 w1 = __ldcs(&W[(size_t)(o0 + 1) * 512 + d4]);
    float4 w2 = __ldcs(&W[(size_t)(o0 + 2) * 512 + d4]);
    float4 w3 = __ldcs(&W[(size_t)(o0 + 3) * 512 + d4]);

#pragma unroll
    for (int ii = 0; ii < ITERS; ii++) {
        float4 c0 = w0, c1 = w1, c2 = w2, c3 = w3;
        int dcur = d4;
        if (ii + 1 < ITERS) {
            d4 += 32;
            w0 = __ldcs(&W[(size_t)(o0 + 0) * 512 + d4]);
            w1 = __ldcs(&W[(size_t)(o0 + 1) * 512 + d4]);
            w2 = __ldcs(&W[(size_t)(o0 + 2) * 512 + d4]);
            w3 = __ldcs(&W[(size_t)(o0 + 3) * 512 + d4]);
        }
#pragma unroll
        for (int b = 0; b < 16; b++) {
            float4 xv = X[b * 512 + dcur];
            acc[0][b] += c0.x * xv.x + c0.y * xv.y + c0.z * xv.z + c0.w * xv.w;
            acc[1][b] += c1.x * xv.x + c1.y * xv.y + c1.z * xv.z + c1.w * xv.w;
            acc[2][b] += c2.x * xv.x + c2.y * xv.y + c2.z * xv.z + c2.w * xv.w;
            acc[3][b] += c3.x * xv.x + c3.y * xv.y + c3.z * xv.z + c3.w * xv.w;
        }
    }

    // ---- smem transpose reduction ----
#pragma unroll
    for (int r = 0; r < 4; r++)
#pragma unroll
        for (int b = 0; b < 16; b++)
            sacc[warp * 64 + r * 16 + b][lane] = acc[r][b];
    __syncthreads();

    const float* bias = a.bias[mi];
    float*       out  = a.out[mi];
    float        sc   = a.scale[mi];
#pragma unroll
    for (int k = 0; k < 2; k++) {
        int oidx = tid + k * 128;               // [0, 256)
        int w2 = oidx >> 6;
        int r2 = (oidx >> 4) & 3;
        int b2 = oidx & 15;
        int row = o0b + w2 * 4 + r2;
        float sum = 0.f;
#pragma unroll
        for (int l = 0; l < 32; l++) sum += sacc[oidx][l];
        if (KSPLIT == 1)
            out[b2 * D_ + row] = (sum + bias[row]) * sc;
        else
            atomicAdd(&out[b2 * D_ + row], sum * sc);
    }
}

// ---------------------------------------------------------------------------
// Split-S flash-decode attention partials with 2-way s-unroll.
// grid = (256 bh, 8 splits), block = 256 (8 warps). Each warp-iteration now
// handles s and s+8: two independent dot products with interleaved shuffle
// trees (ILP=2, 4x16B loads in flight) and one merged online-softmax update
// -- halves the serial shfl-chain count per byte streamed.
// K/V are a 1 GB single-use stream: __ldcs keeps them out of L2's way.
// ---------------------------------------------------------------------------
__global__ __launch_bounds__(256) void attn_partial_kernel(
    const float* __restrict__ pk, const float* __restrict__ pv,
    const float* __restrict__ mask,
    const float* __restrict__ knew, const float* __restrict__ vnew) {
    int bh    = blockIdx.x;
    int split = blockIdx.y;
    int b     = bh >> 4;
    int h     = bh & 15;
    int warp  = threadIdx.x >> 5;
    int lane  = threadIdx.x & 31;

    const float4* q4p = (const float4*)(g_q + b * D_ + h * HD_);
    float4 q4 = q4p[lane];  // q pre-scaled by SCALING

    size_t base = ((size_t)b * SPAST) * D_ + h * HD_;

    float  m = -1e30f, l = 0.f;
    float4 acc = make_float4(0.f, 0.f, 0.f, 0.f);

    int s0 = split * CHUNK + warp;
    int s_end = split * CHUNK + CHUNK;

#pragma unroll 2
    for (int s = s0; s < s_end; s += 16) {
        int sA = s, sB = s + 8;
        const float4* krA = (const float4*)(pk + base + (size_t)sA * D_);
        const float4* vrA = (const float4*)(pv + base + (size_t)sA * D_);
        const float4* krB = (const float4*)(pk + base + (size_t)sB * D_);
        const float4* vrB = (const float4*)(pv + base + (size_t)sB * D_);
        float4 kA = __ldcs(&krA[lane]);
        float4 kB = __ldcs(&krB[lane]);
        float4 vA = __ldcs(&vrA[lane]);
        float4 vB = __ldcs(&vrB[lane]);

        float s1 = kA.x * q4.x + kA.y * q4.y + kA.z * q4.z + kA.w * q4.w;
        float s2 = kB.x * q4.x + kB.y * q4.y + kB.z * q4.z + kB.w * q4.w;
        // Interleaved butterfly trees: the two chains run in parallel.
        s1 += __shfl_xor_sync(0xffffffffu, s1, 16);
        s2 += __shfl_xor_sync(0xffffffffu, s2, 16);
        s1 += __shfl_xor_sync(0xffffffffu, s1, 8);
        s2 += __shfl_xor_sync(0xffffffffu, s2, 8);
        s1 += __shfl_xor_sync(0xffffffffu, s1, 4);
        s2 += __shfl_xor_sync(0xffffffffu, s2, 4);
        s1 += __shfl_xor_sync(0xffffffffu, s1, 2);
        s2 += __shfl_xor_sync(0xffffffffu, s2, 2);
        s1 += __shfl_xor_sync(0xffffffffu, s1, 1);
        s2 += __shfl_xor_sync(0xffffffffu, s2, 1);
        s1 += mask[sA];
        s2 += mask[sB];

        float nm   = fmaxf(m, fmaxf(s1, s2));
        float corr = __expf(m - nm);
        float p1   = __expf(s1 - nm);
        float p2   = __expf(s2 - nm);
        m = nm;
        l = l * corr + p1 + p2;
        acc.x = acc.x * corr + p1 * vA.x + p2 * vB.x;
        acc.y = acc.y * corr + p1 * vA.y + p2 * vB.y;
        acc.z = acc.z * corr + p1 * vA.z + p2 * vB.z;
        acc.w = acc.w * corr + p1 * vA.w + p2 * vB.w;
    }

    // The new token (s = 4096) lives in the last split, handled by warp 0.
    if (split == SPLITS - 1 && warp == 0) {
        const float4* kr = (const float4*)(knew + b * D_ + h * HD_);
        const float4* vr = (const float4*)(vnew + b * D_ + h * HD_);
        float4 k4 = kr[lane];
        float4 v4 = vr[lane];
        float sc = k4.x * q4.x + k4.y * q4.y + k4.z * q4.z + k4.w * q4.w;
        sc += __shfl_xor_sync(0xffffffffu, sc, 16);
        sc += __shfl_xor_sync(0xffffffffu, sc, 8);
        sc += __shfl_xor_sync(0xffffffffu, sc, 4);
        sc += __shfl_xor_sync(0xffffffffu, sc, 2);
        sc += __shfl_xor_sync(0xffffffffu, sc, 1);
        sc += mask[SPAST];
        float nm   = fmaxf(m, sc);
        float corr = __expf(m - nm);
        float p    = __expf(sc - nm);
        m = nm;
        l = l * corr + p;
        acc.x = acc.x * corr + p * v4.x;
        acc.y = acc.y * corr + p * v4.y;
        acc.z = acc.z * corr + p * v4.z;
        acc.w = acc.w * corr + p * v4.w;
    }

    // Combine the 8 warps of this block.
    __shared__ float  sm_m[8], sm_l[8];
    __shared__ float4 sm_acc[8][32];
    sm_acc[warp][lane] = acc;
    if (lane == 0) { sm_m[warp] = m; sm_l[warp] = l; }
    __syncthreads();

    if (threadIdx.x < HD_) {
        int d = threadIdx.x;
        float M = -1e30f;
#pragma unroll
        for (int w = 0; w < 8; w++) M = fmaxf(M, sm_m[w]);
        float L = 0.f, A = 0.f;
        const float* accf = (const float*)sm_acc;
#pragma unroll
        for (int w = 0; w < 8; w++) {
            float e = __expf(sm_m[w] - M);
            L += sm_l[w] * e;
            A += accf[w * HD_ + d] * e;
        }
        int idx = bh * SPLITS + split;
        g_pacc[idx * HD_ + d] = A;
        if (d == 0) { g_pm[idx] = M; g_pl[idx] = L; }
    }
}

// ---------------------------------------------------------------------------
// Combine the 8 split partials per (b,h) AND seed the final output buffer
// with the Wo bias, so the Wo split-K gemv can pure-atomicAdd.
// ---------------------------------------------------------------------------
__global__ __launch_bounds__(128) void attn_combine_kernel(
    float* __restrict__ out, const float* __restrict__ bo) {
    int bh = blockIdx.x;
    int d  = threadIdx.x;

    int oidx = bh * HD_ + d;          // [0, 32768)
    out[oidx] = bo[oidx & (D_ - 1)];  // seed Wo bias

    float M = -1e30f;
#pragma unroll
    for (int i = 0; i < SPLITS; i++) M = fmaxf(M, g_pm[bh * SPLITS + i]);
    float L = 0.f, A = 0.f;
#pragma unroll
    for (int i = 0; i < SPLITS; i++) {
        float e = __expf(g_pm[bh * SPLITS + i] - M);
        L += g_pl[bh * SPLITS + i] * e;
        A += g_pacc[(bh * SPLITS + i) * HD_ + d] * e;
    }
    int b = bh >> 4, h = bh & 15;
    g_attn[b * D_ + h * HD_ + d] = A / L;
}

// ---------------------------------------------------------------------------
extern "C" void kernel_launch(void* const* d_in, const int* in_sizes, int n_in,
                              void* d_out, int out_size) {
    const float* hs   = (const float*)d_in[0];
    const float* pk   = (const float*)d_in[1];
    const float* pv   = (const float*)d_in[2];
    const float* mask = (const float*)d_in[3];
    const float* Wq   = (const float*)d_in[4];
    const float* bq   = (const float*)d_in[5];
    const float* Wk   = (const float*)d_in[6];
    const float* bk   = (const float*)d_in[7];
    const float* Wv   = (const float*)d_in[8];
    const float* bv   = (const float*)d_in[9];
    const float* Wo   = (const float*)d_in[10];
    const float* bo   = (const float*)d_in[11];

    float* out  = (float*)d_out;          // [0, 32768): attn_output
    float* knew = out + B_ * D_;          // [32768, 65536): new_key
    float* vnew = out + 2 * B_ * D_;      // [65536, 98304): new_value

    float* qptr;  cudaGetSymbolAddress((void**)&qptr, g_q);
    float* aptr;  cudaGetSymbolAddress((void**)&aptr, g_attn);

    // 1. Fused QKV projection: 384 full-length blocks, direct bias store.
    GemvArgs a;
    a.W[0] = Wq; a.bias[0] = bq; a.out[0] = qptr; a.scale[0] = SCALING;
    a.W[1] = Wk; a.bias[1] = bk; a.out[1] = knew; a.scale[1] = 1.f;
    a.W[2] = Wv; a.bias[2] = bv; a.out[2] = vnew; a.scale[2] = 1.f;
    gemv_kernel<1><<<384, 128>>>(hs, a);

    // 2. Split-S attention partials (the HBM-bound 1.07 GB stream).
    attn_partial_kernel<<<dim3(B_ * H_, SPLITS), 256>>>(pk, pv, mask, knew, vnew);

    // 3. Combine partials + seed out with Wo bias.
    attn_combine_kernel<<<B_ * H_, 128>>>(out, bo);

    // 4. Output projection: split-K=4 -> 512 blocks, atomics into seeded out.
    GemvArgs ao;
    ao.W[0] = Wo; ao.bias[0] = bo; ao.out[0] = out; ao.scale[0] = 1.f;
    ao.W[1] = Wo; ao.bias[1] = bo; ao.out[1] = out; ao.scale[1] = 1.f;
    ao.W[2] = Wo; ao.bias[2] = bo; ao.out[2] = out; ao.scale[2] = 1.f;
    gemv_kernel<4><<<dim3(128, 4), 128>>>(aptr, ao);
}